// round 8
// baseline (speedup 1.0000x reference)
#include <cuda_runtime.h>
#include <cuda_bf16.h>

// ---------------- problem constants ----------------
constexpr int kNH = 6;
constexpr int kD  = 768;
constexpr int kHD = 128;
constexpr int kB  = 2;
constexpr int kT  = 2048;
constexpr int kBT = kB * kT;          // 4096
constexpr float kEPS = 1e-6f;

constexpr int PITCH = 132;            // smem pitch for 128-wide tiles (float4-aligned, conflict-free)
constexpr int GP    = 132;            // gemm smem pitch

// ---------------- device scratch (no allocation allowed) ----------------
__device__ float d_Z   [kNH * kBT * kHD];   // x @ phi   (inner)
__device__ float d_ZPSI[kNH * kBT * kHD];   // x @ psi   (query)
__device__ float d_P   [kNH * kBT * kHD];   // g @ (x*s)
__device__ float d_Q   [kNH * kBT * kHD];   // scan output per head
__device__ float d_SX  [kNH * kBT];         // sum_d x*s
__device__ float d_G   [kNH * kHD * kHD];   // g g^T
__device__ float d_G2  [kNH * kHD * kHD];   // g diag(s^2) g^T
__device__ float d_g1  [kNH * kHD];
__device__ float d_v2  [kNH * kHD];
__device__ float d_vbs [kNH * kHD];
__device__ float d_S2  [kNH];
__device__ float d_SBS [kNH];
__device__ int   d_flag[1];

__device__ __forceinline__ float warpsum(float v) {
    #pragma unroll
    for (int o = 16; o > 0; o >>= 1) v += __shfl_xor_sync(0xFFFFFFFFu, v, o);
    return v;
}

// ---------------- fast-path detection: ln_scale==1, ln_bias==0 ----------------
__global__ void flag_kernel(const float* __restrict__ s, const float* __restrict__ b) {
    __shared__ int sok;
    if (threadIdx.x == 0) sok = 1;
    __syncthreads();
    int ok = 1;
    for (int i = threadIdx.x; i < kNH * kD; i += 256)
        ok &= (s[i] == 1.0f) && (b[i] == 0.0f);
    if (!ok) atomicAnd(&sok, 0);
    __syncthreads();
    if (threadIdx.x == 0) d_flag[0] = sok;
}

// ---------------- per-head constants G = g g^T (mode 0), G2 = g diag(s^2) g^T (mode 1) ----------------
__global__ void __launch_bounds__(256) consts_kernel(const float* __restrict__ g,
                                                     const float* __restrict__ s) {
    const int k = blockIdx.x;
    const int mode = blockIdx.y;     // 0 -> G, 1 -> G2
    __shared__ float gsh[128 * 33];
    __shared__ float wsh[32];
    const int tid = threadIdx.x;
    const int tx = tid & 15, ty = tid >> 4;
    float acc[8][8];
    #pragma unroll
    for (int r = 0; r < 8; r++)
        #pragma unroll
        for (int c = 0; c < 8; c++) acc[r][c] = 0.f;

    for (int d0 = 0; d0 < kD; d0 += 32) {
        for (int f = tid; f < 128 * 32; f += 256) {
            int i = f >> 5, dd = f & 31;
            gsh[i * 33 + dd] = g[(k * kHD + i) * kD + d0 + dd];
        }
        if (tid < 32) {
            float sv = s[k * kD + d0 + tid];
            wsh[tid] = mode ? sv * sv : 1.0f;
        }
        __syncthreads();
        #pragma unroll 4
        for (int dd = 0; dd < 32; dd++) {
            float wv = wsh[dd];
            float a[8], bb[8];
            #pragma unroll
            for (int r = 0; r < 8; r++) a[r] = gsh[(ty * 8 + r) * 33 + dd] * wv;
            #pragma unroll
            for (int c = 0; c < 8; c++) bb[c] = gsh[(tx * 8 + c) * 33 + dd];
            #pragma unroll
            for (int r = 0; r < 8; r++)
                #pragma unroll
                for (int c = 0; c < 8; c++) acc[r][c] = fmaf(a[r], bb[c], acc[r][c]);
        }
        __syncthreads();
    }
    float* dst = (mode ? d_G2 : d_G) + k * kHD * kHD;
    #pragma unroll
    for (int r = 0; r < 8; r++)
        #pragma unroll
        for (int c = 0; c < 8; c++)
            dst[(ty * 8 + r) * kHD + tx * 8 + c] = acc[r][c];
}

// ---------------- row stats: g1, v2, vbs, S2, SBS ----------------
__global__ void rowstats_kernel(const float* __restrict__ g,
                                const float* __restrict__ s,
                                const float* __restrict__ b) {
    const int k = blockIdx.x;
    const int tid = threadIdx.x;   // 256
    if (tid < 128) {
        float a1 = 0.f, a2 = 0.f, a3 = 0.f;
        const float* grow = g + (k * kHD + tid) * kD;
        const float* srow = s + k * kD;
        const float* brow = b + k * kD;
        for (int d = 0; d < kD; d++) {
            float gv = grow[d], sv = srow[d], bv = brow[d];
            a1 += gv;
            a2 = fmaf(gv, sv * sv, a2);
            a3 = fmaf(gv, bv * sv, a3);
        }
        d_g1[k * kHD + tid]  = a1;
        d_v2[k * kHD + tid]  = a2;
        d_vbs[k * kHD + tid] = a3;
    }
    float s2p = 0.f, sbp = 0.f;
    for (int d = tid; d < kD; d += 256) {
        float sv = s[k * kD + d], bv = b[k * kD + d];
        s2p = fmaf(sv, sv, s2p);
        sbp = fmaf(bv, sv, sbp);
    }
    __shared__ float red[512];
    red[tid] = s2p; red[256 + tid] = sbp;
    __syncthreads();
    for (int o = 128; o > 0; o >>= 1) {
        if (tid < o) { red[tid] += red[tid + o]; red[256 + tid] += red[256 + tid + o]; }
        __syncthreads();
    }
    if (tid == 0) { d_S2[k] = red[0]; d_SBS[k] = red[256]; }
}

// ---------------- SX[k][bt] = sum_d X[bt][d] * s[k][d] ----------------
__global__ void sx_kernel(const float* __restrict__ X, const float* __restrict__ s) {
    const int bt = blockIdx.x;
    const int w = threadIdx.x >> 5;      // 0..5 (192 threads)
    const int lane = threadIdx.x & 31;
    float acc = 0.f;
    for (int d0 = lane * 4; d0 < kD; d0 += 128) {
        float4 xv = *(const float4*)&X[bt * kD + d0];
        float4 sv = *(const float4*)&s[w * kD + d0];
        acc = fmaf(xv.x, sv.x, acc);
        acc = fmaf(xv.y, sv.y, acc);
        acc = fmaf(xv.z, sv.z, acc);
        acc = fmaf(xv.w, sv.w, acc);
    }
    acc = warpsum(acc);
    if (lane == 0) d_SX[w * kBT + bt] = acc;
}

// ---------------- projection GEMMs: Z = X@phi, ZPSI = X@psi, P = X @ (g*s)^T ----------------
// which = blockIdx.z % 3 : 0 -> Z (phi), 1 -> ZPSI (psi), 2 -> P (g scaled by s, transposed)
__global__ void __launch_bounds__(256) gemm_proj_kernel(const float* __restrict__ X,
                                                        const float* __restrict__ phi,
                                                        const float* __restrict__ psi,
                                                        const float* __restrict__ g,
                                                        const float* __restrict__ s) {
    const int which = blockIdx.z % 3;
    const int head  = blockIdx.z / 3;
    const int m0 = blockIdx.y * 128;
    __shared__ float As[16 * GP];
    __shared__ float Bs[16 * GP];
    const int tid = threadIdx.x;
    const int tx = tid & 15, ty = tid >> 4;
    float acc[8][8];
    #pragma unroll
    for (int r = 0; r < 8; r++)
        #pragma unroll
        for (int c = 0; c < 8; c++) acc[r][c] = 0.f;

    const float* Bsrc = (which == 0) ? phi : psi;

    for (int k0 = 0; k0 < kD; k0 += 16) {
        // A tile (128x16) transposed into As[kk][m]
        {
            int m = tid >> 2, kq = tid & 3;
            #pragma unroll
            for (int h2 = 0; h2 < 2; h2++) {
                int mm = m + h2 * 64;
                float4 v = *(const float4*)&X[(size_t)(m0 + mm) * kD + k0 + kq * 4];
                As[(kq * 4 + 0) * GP + mm] = v.x;
                As[(kq * 4 + 1) * GP + mm] = v.y;
                As[(kq * 4 + 2) * GP + mm] = v.z;
                As[(kq * 4 + 3) * GP + mm] = v.w;
            }
        }
        // B tile (16x128)
        if (which < 2) {
            int f = tid;
            #pragma unroll
            for (int it = 0; it < 2; it++, f += 256) {
                int kk = f >> 5, n4 = f & 31;
                float4 v = *(const float4*)&Bsrc[(size_t)(head * kD + k0 + kk) * kHD + n4 * 4];
                *(float4*)&Bs[kk * GP + n4 * 4] = v;
            }
        } else {
            int f = tid;
            #pragma unroll
            for (int it = 0; it < 2; it++, f += 256) {
                int jj = f >> 2, kq = f & 3;
                float4 gv = *(const float4*)&g[(size_t)(head * kHD + jj) * kD + k0 + kq * 4];
                float4 sv = *(const float4*)&s[head * kD + k0 + kq * 4];
                Bs[(kq * 4 + 0) * GP + jj] = gv.x * sv.x;
                Bs[(kq * 4 + 1) * GP + jj] = gv.y * sv.y;
                Bs[(kq * 4 + 2) * GP + jj] = gv.z * sv.z;
                Bs[(kq * 4 + 3) * GP + jj] = gv.w * sv.w;
            }
        }
        __syncthreads();
        #pragma unroll
        for (int kk = 0; kk < 16; kk++) {
            float a[8], bb[8];
            *(float4*)&a[0]  = *(const float4*)&As[kk * GP + ty * 8];
            *(float4*)&a[4]  = *(const float4*)&As[kk * GP + ty * 8 + 4];
            *(float4*)&bb[0] = *(const float4*)&Bs[kk * GP + tx * 8];
            *(float4*)&bb[4] = *(const float4*)&Bs[kk * GP + tx * 8 + 4];
            #pragma unroll
            for (int r = 0; r < 8; r++)
                #pragma unroll
                for (int c = 0; c < 8; c++) acc[r][c] = fmaf(a[r], bb[c], acc[r][c]);
        }
        __syncthreads();
    }
    float* Cdst = ((which == 0) ? d_Z : (which == 1) ? d_ZPSI : d_P) + (size_t)head * kBT * kHD;
    #pragma unroll
    for (int r = 0; r < 8; r++) {
        int m = m0 + ty * 8 + r;
        *(float4*)&Cdst[(size_t)m * kHD + tx * 8]     = make_float4(acc[r][0], acc[r][1], acc[r][2], acc[r][3]);
        *(float4*)&Cdst[(size_t)m * kHD + tx * 8 + 4] = make_float4(acc[r][4], acc[r][5], acc[r][6], acc[r][7]);
    }
}

// ---------------- output GEMM: out[bt][d] = sum_k sum_j Q[k][bt][j] * h[k][j][d] ----------------
__global__ void __launch_bounds__(256) gemm_out_kernel(const float* __restrict__ h,
                                                       float* __restrict__ out) {
    const int n0 = blockIdx.x * 128;   // over D = 768
    const int m0 = blockIdx.y * 128;   // over BT = 4096
    __shared__ float As[16 * GP];
    __shared__ float Bs[16 * GP];
    const int tid = threadIdx.x;
    const int tx = tid & 15, ty = tid >> 4;
    float acc[8][8];
    #pragma unroll
    for (int r = 0; r < 8; r++)
        #pragma unroll
        for (int c = 0; c < 8; c++) acc[r][c] = 0.f;

    for (int k0 = 0; k0 < kNH * kHD; k0 += 16) {
        const int head = k0 >> 7;
        const int j0 = k0 & 127;
        const float* Aq = d_Q + (size_t)head * kBT * kHD;
        {
            int m = tid >> 2, kq = tid & 3;
            #pragma unroll
            for (int h2 = 0; h2 < 2; h2++) {
                int mm = m + h2 * 64;
                float4 v = *(const float4*)&Aq[(size_t)(m0 + mm) * kHD + j0 + kq * 4];
                As[(kq * 4 + 0) * GP + mm] = v.x;
                As[(kq * 4 + 1) * GP + mm] = v.y;
                As[(kq * 4 + 2) * GP + mm] = v.z;
                As[(kq * 4 + 3) * GP + mm] = v.w;
            }
        }
        {
            int f = tid;
            #pragma unroll
            for (int it = 0; it < 2; it++, f += 256) {
                int kk = f >> 5, n4 = f & 31;
                float4 v = *(const float4*)&h[(size_t)(k0 + kk) * kD + n0 + n4 * 4];
                *(float4*)&Bs[kk * GP + n4 * 4] = v;
            }
        }
        __syncthreads();
        #pragma unroll
        for (int kk = 0; kk < 16; kk++) {
            float a[8], bb[8];
            *(float4*)&a[0]  = *(const float4*)&As[kk * GP + ty * 8];
            *(float4*)&a[4]  = *(const float4*)&As[kk * GP + ty * 8 + 4];
            *(float4*)&bb[0] = *(const float4*)&Bs[kk * GP + tx * 8];
            *(float4*)&bb[4] = *(const float4*)&Bs[kk * GP + tx * 8 + 4];
            #pragma unroll
            for (int r = 0; r < 8; r++)
                #pragma unroll
                for (int c = 0; c < 8; c++) acc[r][c] = fmaf(a[r], bb[c], acc[r][c]);
        }
        __syncthreads();
    }
    #pragma unroll
    for (int r = 0; r < 8; r++) {
        int m = m0 + ty * 8 + r;
        *(float4*)&out[(size_t)m * kD + n0 + tx * 8]     = make_float4(acc[r][0], acc[r][1], acc[r][2], acc[r][3]);
        *(float4*)&out[(size_t)m * kD + n0 + tx * 8 + 4] = make_float4(acc[r][4], acc[r][5], acc[r][6], acc[r][7]);
    }
}

// ---------------- the sequential scan: one CTA per (head, batch) ----------------
// W (128x128) lives in registers: thread (j = tid&127, half = tid>>7) owns rows half*64..+63 of column j.
constexpr int SCAN_SMEM_FLOATS =
    2 * 128 * PITCH   // Gsh, G2sh
    + 3 * 256         // zsh, zpsh, Psh (double buffered)
    + 128             // ysh
    + 4 * 256         // py, pp, pgy, pg2y
    + 3 * 128         // Gysh, G2ysh, dysh
    + 3 * 128         // g1sh, v2sh, vbssh
    + 16;             // scal[0..6], sx double buffer at [8],[9]
constexpr int SCAN_SMEM_BYTES = SCAN_SMEM_FLOATS * 4;

__global__ void __launch_bounds__(256, 1) scan_kernel(const float* __restrict__ W0) {
    extern __shared__ float sm[];
    float* Gsh   = sm;
    float* G2sh  = Gsh + 128 * PITCH;
    float* zsh   = G2sh + 128 * PITCH;
    float* zpsh  = zsh + 256;
    float* Psh   = zpsh + 256;
    float* ysh   = Psh + 256;
    float* py    = ysh + 128;
    float* pp    = py + 256;
    float* pgy   = pp + 256;
    float* pg2y  = pgy + 256;
    float* Gysh  = pg2y + 256;
    float* G2ysh = Gysh + 128;
    float* dysh  = G2ysh + 128;
    float* g1sh  = dysh + 128;
    float* v2sh  = g1sh + 128;
    float* vbssh = v2sh + 128;
    float* scal  = vbssh + 128;

    const int k = blockIdx.x;
    const int b = blockIdx.y;
    const int tid = threadIdx.x;
    const int j = tid & 127;
    const int half = tid >> 7;
    const bool fast = (d_flag[0] != 0);

    // ---- init ----
    for (int idx = tid; idx < kHD * kHD; idx += 256) {
        int i = idx >> 7, jj = idx & 127;
        Gsh[i * PITCH + jj] = d_G[k * kHD * kHD + idx];
        if (!fast) G2sh[i * PITCH + jj] = d_G2[k * kHD * kHD + idx];
    }
    const int seqbase = (k * kBT + b * kT) * kHD;
    if (tid < 128) {
        g1sh[tid]  = d_g1[k * kHD + tid];
        v2sh[tid]  = d_v2[k * kHD + tid];
        vbssh[tid] = d_vbs[k * kHD + tid];
        dysh[tid]  = 0.f;
        zsh[128 + tid] = 0.f;          // buffer 1 must be NaN-free for the t=0 (no-op) update
        zsh[tid]  = d_Z[seqbase + tid];
        zpsh[tid] = d_ZPSI[seqbase + tid];
        Psh[tid]  = d_P[seqbase + tid];
        if (tid == 0) scal[8] = d_SX[k * kBT + b * kT];
    }
    const float S2v  = d_S2[k];
    const float SBSv = d_SBS[k];

    float W[64];
    #pragma unroll
    for (int r = 0; r < 64; r++)
        W[r] = W0[(k * kHD + half * 64 + r) * kHD + j];

    __syncthreads();

    const float cc = (float)kNH / (float)kD;

    for (int t = 0; t < kT; ++t) {
        const int cur = t & 1;
        const int nb = cur ^ 1;
        const float dyO = dysh[j];     // dy from step t-1 (zero at t=0)

        // prefetch next token into registers (hidden behind stage A compute)
        float nz = 0.f, nP = 0.f, nzp = 0.f, nsx = 0.f;
        if (t + 1 < kT) {
            int pb = seqbase + (t + 1) * kHD;
            if (tid < 128) {
                nz = d_Z[pb + tid];
                nP = d_P[pb + tid];
                if (tid == 0) nsx = d_SX[k * kBT + b * kT + t + 1];
            } else {
                nzp = d_ZPSI[pb + (tid - 128)];
            }
        }

        // ---- Stage A: W -= z_{t-1} dy^T (fused), then y = z_t @ W, p = zpsi_t @ W partials ----
        {
            const float* zo = zsh  + nb  * 128 + half * 64;
            const float* zc = zsh  + cur * 128 + half * 64;
            const float* zp = zpsh + cur * 128 + half * 64;
            float ypart = 0.f, ppart = 0.f;
            #pragma unroll
            for (int r = 0; r < 64; r += 4) {
                const float4 zov = *(const float4*)(zo + r);
                const float4 zcv = *(const float4*)(zc + r);
                const float4 zpv = *(const float4*)(zp + r);
                float w;
                w = fmaf(-zov.x, dyO, W[r+0]); ypart = fmaf(zcv.x, w, ypart); ppart = fmaf(zpv.x, w, ppart); W[r+0] = w;
                w = fmaf(-zov.y, dyO, W[r+1]); ypart = fmaf(zcv.y, w, ypart); ppart = fmaf(zpv.y, w, ppart); W[r+1] = w;
                w = fmaf(-zov.z, dyO, W[r+2]); ypart = fmaf(zcv.z, w, ypart); ppart = fmaf(zpv.z, w, ppart); W[r+2] = w;
                w = fmaf(-zov.w, dyO, W[r+3]); ypart = fmaf(zcv.w, w, ypart); ppart = fmaf(zpv.w, w, ppart); W[r+3] = w;
            }
            py[half * 128 + j] = ypart;
            pp[half * 128 + j] = ppart;
        }
        __syncthreads();   // S1

        // ---- Stage B0: combine y halves; stash prefetched token into the (now free) other buffer ----
        if (tid < 128) {
            ysh[tid] = py[tid] + py[128 + tid];
            zsh[nb * 128 + tid] = nz;
            Psh[nb * 128 + tid] = nP;
            if (tid == 0) scal[8 + nb] = nsx;
        } else {
            zpsh[nb * 128 + (tid - 128)] = nzp;
        }
        __syncthreads();   // S2

        // ---- Stage B1: Gy (and G2y) half-row partials ----
        {
            const float* Grow  = Gsh  + j * PITCH + half * 64;
            const float* G2row = G2sh + j * PITCH + half * 64;
            const float* yv = ysh + half * 64;
            float ag = 0.f, ag2 = 0.f;
            #pragma unroll
            for (int q4 = 0; q4 < 64; q4 += 4) {
                const float4 y4 = *(const float4*)(yv + q4);
                const float4 g4 = *(const float4*)(Grow + q4);
                ag = fmaf(g4.x, y4.x, ag); ag = fmaf(g4.y, y4.y, ag);
                ag = fmaf(g4.z, y4.z, ag); ag = fmaf(g4.w, y4.w, ag);
                if (!fast) {
                    const float4 h4 = *(const float4*)(G2row + q4);
                    ag2 = fmaf(h4.x, y4.x, ag2); ag2 = fmaf(h4.y, y4.y, ag2);
                    ag2 = fmaf(h4.z, y4.z, ag2); ag2 = fmaf(h4.w, y4.w, ag2);
                }
            }
            pgy[half * 128 + j] = ag;
            if (!fast) pg2y[half * 128 + j] = ag2;
        }
        __syncthreads();   // S3

        // ---- Stage C: combine Gy/G2y; 5 dot products on the other half ----
        if (tid < 128) {
            float gv = pgy[tid] + pgy[128 + tid];
            Gysh[tid] = gv;
            G2ysh[tid] = fast ? gv : (pg2y[tid] + pg2y[128 + tid]);
        } else {
            const int w = (tid >> 5) & 3;
            const int lane = tid & 31;
            const float4 y4 = *(const float4*)&ysh[lane * 4];
            if (w == 0) {
                float4 a4 = *(const float4*)&g1sh[lane * 4];
                float v = y4.x * a4.x + y4.y * a4.y + y4.z * a4.z + y4.w * a4.w;
                v = warpsum(v); if (lane == 0) scal[0] = v;           // g1.y
                float4 zc4 = *(const float4*)&zsh[cur * 128 + lane * 4];
                float4 zp4 = *(const float4*)&zpsh[cur * 128 + lane * 4];
                float v2 = zc4.x * zp4.x + zc4.y * zp4.y + zc4.z * zp4.z + zc4.w * zp4.w;
                v2 = warpsum(v2); if (lane == 0) scal[4] = v2;        // z.zpsi
            } else if (w == 1) {
                float4 a4 = *(const float4*)&v2sh[lane * 4];
                float v = y4.x * a4.x + y4.y * a4.y + y4.z * a4.z + y4.w * a4.w;
                v = warpsum(v); if (lane == 0) scal[1] = v;           // v2.y
            } else if (w == 2) {
                float4 a4 = *(const float4*)&vbssh[lane * 4];
                float v = y4.x * a4.x + y4.y * a4.y + y4.z * a4.z + y4.w * a4.w;
                v = warpsum(v); if (lane == 0) scal[2] = v;           // vbs.y
            } else {
                float4 a4 = *(const float4*)&Psh[cur * 128 + lane * 4];
                float v = y4.x * a4.x + y4.y * a4.y + y4.z * a4.z + y4.w * a4.w;
                v = warpsum(v); if (lane == 0) scal[3] = v;           // P.y
            }
        }
        __syncthreads();   // S4

        // ---- Stage D: su2 = y.Gy, q2 = y.G2y ----
        if (tid < 64) {
            const int w = tid >> 5, lane = tid & 31;
            const float4 y4 = *(const float4*)&ysh[lane * 4];
            const float* Mv = w ? G2ysh : Gysh;
            const float4 m4 = *(const float4*)&Mv[lane * 4];
            float v = y4.x * m4.x + y4.y * m4.y + y4.z * m4.z + y4.w * m4.w;
            v = warpsum(v); if (lane == 0) scal[5 + w] = v;
        }
        __syncthreads();   // S5

        // ---- Stage E: scalars, dy, q ----
        if (tid < 128) {
            const float g1y = scal[0], v2y = scal[1], vbsy = scal[2], Pty = scal[3];
            const float zz = scal[4], su2 = scal[5], q2 = scal[6], SXt = scal[8 + cur];
            const float invD = 1.f / (float)kD;
            const float mu = g1y * invD;
            const float var = su2 * invD - mu * mu;
            const float rr = rsqrtf(var + kEPS);
            const float r2 = rr * rr;
            const float mdn  = (cc * invD) * (rr * (v2y - mu * S2v) + SBSv - SXt);
            const float mdnn = (cc * invD) * (r2 * (q2 - 2.f * mu * v2y + mu * mu * S2v)
                                              + rr * (vbsy - mu * SBSv)
                                              - rr * (Pty - mu * SXt));
            const float a1 = cc * r2;
            const float a2 = -r2 * mdnn;
            const float a3 = -cc * rr;
            const float a4 = -cc * r2 * mu;
            const float a5 = cc * rr;
            const float a6 = rr * (mdnn * rr * mu - mdn);
            const int i = tid;
            float dyv = a1 * G2ysh[i] + a2 * Gysh[i] + a3 * Psh[cur * 128 + i]
                      + a4 * v2sh[i] + a5 * vbssh[i] + a6 * g1sh[i];
            dysh[i] = dyv;
            float qv = (pp[i] + pp[128 + i]) - zz * dyv;
            d_Q[seqbase + t * kHD + i] = qv;
        }
        __syncthreads();   // S6
    }
}

// ---------------- launch ----------------
extern "C" void kernel_launch(void* const* d_in, const int* in_sizes, int n_in,
                              void* d_out, int out_size) {
    const float* X   = (const float*)d_in[0];   // batch (B,T,D)
    const float* psi = (const float*)d_in[1];   // psi_k (NH,D,HD)
    const float* phi = (const float*)d_in[2];   // phi_k (NH,D,HD)
    const float* W0  = (const float*)d_in[3];   // (NH,HD,HD)
    const float* g   = (const float*)d_in[4];   // (NH,HD,D)
    const float* h   = (const float*)d_in[5];   // (NH,HD,D) -> contiguous (768,768)
    const float* lns = (const float*)d_in[6];   // (NH,D)
    const float* lnb = (const float*)d_in[7];   // (NH,D)
    float* out = (float*)d_out;
    (void)in_sizes; (void)n_in; (void)out_size;

    cudaFuncSetAttribute(scan_kernel, cudaFuncAttributeMaxDynamicSharedMemorySize, SCAN_SMEM_BYTES);

    flag_kernel<<<1, 256>>>(lns, lnb);
    consts_kernel<<<dim3(kNH, 2), 256>>>(g, lns);
    rowstats_kernel<<<kNH, 256>>>(g, lns, lnb);
    sx_kernel<<<kBT, 192>>>(X, lns);
    gemm_proj_kernel<<<dim3(1, kBT / 128, 3 * kNH), 256>>>(X, phi, psi, g, lns);
    scan_kernel<<<dim3(kNH, kB), 256, SCAN_SMEM_BYTES>>>(W0);
    gemm_out_kernel<<<dim3(kD / 128, kBT / 128), 256>>>(h, out);
}

// round 9
// speedup vs baseline: 1.0211x; 1.0211x over previous
#include <cuda_runtime.h>
#include <cuda_bf16.h>

// ---------------- problem constants ----------------
constexpr int kNH = 6;
constexpr int kD  = 768;
constexpr int kHD = 128;
constexpr int kB  = 2;
constexpr int kT  = 2048;
constexpr int kBT = kB * kT;          // 4096
constexpr float kEPS = 1e-6f;

constexpr int PITCH = 132;            // smem pitch (float4-aligned, conflict-reducing)
constexpr int GP    = 132;            // gemm smem pitch

typedef unsigned long long ull;

// ---------------- device scratch (no allocation allowed) ----------------
__device__ float d_Z   [kNH * kBT * kHD];   // x @ phi   (inner)
__device__ float d_ZPSI[kNH * kBT * kHD];   // x @ psi   (query)
__device__ float d_P   [kNH * kBT * kHD];   // g @ (x*s)
__device__ float d_Q   [kNH * kBT * kHD];   // scan output per head
__device__ float d_SX  [kNH * kBT];         // sum_d x*s
__device__ float d_G   [kNH * kHD * kHD];   // g g^T
__device__ float d_G2  [kNH * kHD * kHD];   // g diag(s^2) g^T
__device__ float d_g1  [kNH * kHD];
__device__ float d_v2  [kNH * kHD];
__device__ float d_vbs [kNH * kHD];
__device__ float d_S2  [kNH];
__device__ float d_SBS [kNH];
__device__ int   d_flag[1];

// ---------------- f32x2 packed helpers ----------------
__device__ __forceinline__ ull fma2(ull a, ull b, ull c) {
    ull d;
    asm("fma.rn.f32x2 %0, %1, %2, %3;" : "=l"(d) : "l"(a), "l"(b), "l"(c));
    return d;
}
__device__ __forceinline__ ull pack2(float lo, float hi) {
    ull r;
    asm("mov.b64 %0, {%1, %2};" : "=l"(r) : "f"(lo), "f"(hi));
    return r;
}
__device__ __forceinline__ float hsum2(ull v) {
    float lo, hi;
    asm("mov.b64 {%0, %1}, %2;" : "=f"(lo), "=f"(hi) : "l"(v));
    return lo + hi;
}
__device__ __forceinline__ float warpsum(float v) {
    #pragma unroll
    for (int o = 16; o > 0; o >>= 1) v += __shfl_xor_sync(0xFFFFFFFFu, v, o);
    return v;
}

// ---------------- fast-path detection: ln_scale==1, ln_bias==0 ----------------
__global__ void flag_kernel(const float* __restrict__ s, const float* __restrict__ b) {
    __shared__ int sok;
    if (threadIdx.x == 0) sok = 1;
    __syncthreads();
    int ok = 1;
    for (int i = threadIdx.x; i < kNH * kD; i += 256)
        ok &= (s[i] == 1.0f) && (b[i] == 0.0f);
    if (!ok) atomicAnd(&sok, 0);
    __syncthreads();
    if (threadIdx.x == 0) d_flag[0] = sok;
}

// ---------------- per-head constants G = g g^T (mode 0), G2 = g diag(s^2) g^T (mode 1) ----------------
__global__ void __launch_bounds__(256) consts_kernel(const float* __restrict__ g,
                                                     const float* __restrict__ s) {
    const int k = blockIdx.x;
    const int mode = blockIdx.y;     // 0 -> G, 1 -> G2
    __shared__ float gsh[128 * 33];
    __shared__ float wsh[32];
    const int tid = threadIdx.x;
    const int tx = tid & 15, ty = tid >> 4;
    float acc[8][8];
    #pragma unroll
    for (int r = 0; r < 8; r++)
        #pragma unroll
        for (int c = 0; c < 8; c++) acc[r][c] = 0.f;

    for (int d0 = 0; d0 < kD; d0 += 32) {
        for (int f = tid; f < 128 * 32; f += 256) {
            int i = f >> 5, dd = f & 31;
            gsh[i * 33 + dd] = g[(k * kHD + i) * kD + d0 + dd];
        }
        if (tid < 32) {
            float sv = s[k * kD + d0 + tid];
            wsh[tid] = mode ? sv * sv : 1.0f;
        }
        __syncthreads();
        #pragma unroll 4
        for (int dd = 0; dd < 32; dd++) {
            float wv = wsh[dd];
            float a[8], bb[8];
            #pragma unroll
            for (int r = 0; r < 8; r++) a[r] = gsh[(ty * 8 + r) * 33 + dd] * wv;
            #pragma unroll
            for (int c = 0; c < 8; c++) bb[c] = gsh[(tx * 8 + c) * 33 + dd];
            #pragma unroll
            for (int r = 0; r < 8; r++)
                #pragma unroll
                for (int c = 0; c < 8; c++) acc[r][c] = fmaf(a[r], bb[c], acc[r][c]);
        }
        __syncthreads();
    }
    float* dst = (mode ? d_G2 : d_G) + k * kHD * kHD;
    #pragma unroll
    for (int r = 0; r < 8; r++)
        #pragma unroll
        for (int c = 0; c < 8; c++)
            dst[(ty * 8 + r) * kHD + tx * 8 + c] = acc[r][c];
}

// ---------------- row stats: g1, v2, vbs, S2, SBS ----------------
__global__ void rowstats_kernel(const float* __restrict__ g,
                                const float* __restrict__ s,
                                const float* __restrict__ b) {
    const int k = blockIdx.x;
    const int tid = threadIdx.x;   // 256
    if (tid < 128) {
        float a1 = 0.f, a2 = 0.f, a3 = 0.f;
        const float* grow = g + (k * kHD + tid) * kD;
        const float* srow = s + k * kD;
        const float* brow = b + k * kD;
        for (int d = 0; d < kD; d++) {
            float gv = grow[d], sv = srow[d], bv = brow[d];
            a1 += gv;
            a2 = fmaf(gv, sv * sv, a2);
            a3 = fmaf(gv, bv * sv, a3);
        }
        d_g1[k * kHD + tid]  = a1;
        d_v2[k * kHD + tid]  = a2;
        d_vbs[k * kHD + tid] = a3;
    }
    float s2p = 0.f, sbp = 0.f;
    for (int d = tid; d < kD; d += 256) {
        float sv = s[k * kD + d], bv = b[k * kD + d];
        s2p = fmaf(sv, sv, s2p);
        sbp = fmaf(bv, sv, sbp);
    }
    __shared__ float red[512];
    red[tid] = s2p; red[256 + tid] = sbp;
    __syncthreads();
    for (int o = 128; o > 0; o >>= 1) {
        if (tid < o) { red[tid] += red[tid + o]; red[256 + tid] += red[256 + tid + o]; }
        __syncthreads();
    }
    if (tid == 0) { d_S2[k] = red[0]; d_SBS[k] = red[256]; }
}

// ---------------- SX[k][bt] = sum_d X[bt][d] * s[k][d] ----------------
__global__ void sx_kernel(const float* __restrict__ X, const float* __restrict__ s) {
    const int bt = blockIdx.x;
    const int w = threadIdx.x >> 5;      // 0..5 (192 threads)
    const int lane = threadIdx.x & 31;
    float acc = 0.f;
    for (int d0 = lane * 4; d0 < kD; d0 += 128) {
        float4 xv = *(const float4*)&X[bt * kD + d0];
        float4 sv = *(const float4*)&s[w * kD + d0];
        acc = fmaf(xv.x, sv.x, acc);
        acc = fmaf(xv.y, sv.y, acc);
        acc = fmaf(xv.z, sv.z, acc);
        acc = fmaf(xv.w, sv.w, acc);
    }
    acc = warpsum(acc);
    if (lane == 0) d_SX[w * kBT + bt] = acc;
}

// ---------------- projection GEMMs: Z = X@phi, ZPSI = X@psi, P = X @ (g*s)^T ----------------
__global__ void __launch_bounds__(256) gemm_proj_kernel(const float* __restrict__ X,
                                                        const float* __restrict__ phi,
                                                        const float* __restrict__ psi,
                                                        const float* __restrict__ g,
                                                        const float* __restrict__ s) {
    const int which = blockIdx.z % 3;
    const int head  = blockIdx.z / 3;
    const int m0 = blockIdx.y * 128;
    __shared__ float As[16 * GP];
    __shared__ float Bs[16 * GP];
    const int tid = threadIdx.x;
    const int tx = tid & 15, ty = tid >> 4;
    ull acc2[8][4];
    #pragma unroll
    for (int r = 0; r < 8; r++)
        #pragma unroll
        for (int c = 0; c < 4; c++) acc2[r][c] = 0ULL;

    const float* Bsrc = (which == 0) ? phi : psi;

    for (int k0 = 0; k0 < kD; k0 += 16) {
        {
            int m = tid >> 2, kq = tid & 3;
            #pragma unroll
            for (int h2 = 0; h2 < 2; h2++) {
                int mm = m + h2 * 64;
                float4 v = *(const float4*)&X[(size_t)(m0 + mm) * kD + k0 + kq * 4];
                As[(kq * 4 + 0) * GP + mm] = v.x;
                As[(kq * 4 + 1) * GP + mm] = v.y;
                As[(kq * 4 + 2) * GP + mm] = v.z;
                As[(kq * 4 + 3) * GP + mm] = v.w;
            }
        }
        if (which < 2) {
            int f = tid;
            #pragma unroll
            for (int it = 0; it < 2; it++, f += 256) {
                int kk = f >> 5, n4 = f & 31;
                float4 v = *(const float4*)&Bsrc[(size_t)(head * kD + k0 + kk) * kHD + n4 * 4];
                *(float4*)&Bs[kk * GP + n4 * 4] = v;
            }
        } else {
            int f = tid;
            #pragma unroll
            for (int it = 0; it < 2; it++, f += 256) {
                int jj = f >> 2, kq = f & 3;
                float4 gv = *(const float4*)&g[(size_t)(head * kHD + jj) * kD + k0 + kq * 4];
                float4 sv = *(const float4*)&s[head * kD + k0 + kq * 4];
                Bs[(kq * 4 + 0) * GP + jj] = gv.x * sv.x;
                Bs[(kq * 4 + 1) * GP + jj] = gv.y * sv.y;
                Bs[(kq * 4 + 2) * GP + jj] = gv.z * sv.z;
                Bs[(kq * 4 + 3) * GP + jj] = gv.w * sv.w;
            }
        }
        __syncthreads();
        #pragma unroll
        for (int kk = 0; kk < 16; kk++) {
            float a[8];
            *(float4*)&a[0]  = *(const float4*)&As[kk * GP + ty * 8];
            *(float4*)&a[4]  = *(const float4*)&As[kk * GP + ty * 8 + 4];
            ulonglong2 b0 = *(const ulonglong2*)&Bs[kk * GP + tx * 8];
            ulonglong2 b1 = *(const ulonglong2*)&Bs[kk * GP + tx * 8 + 4];
            #pragma unroll
            for (int r = 0; r < 8; r++) {
                ull a2 = pack2(a[r], a[r]);
                acc2[r][0] = fma2(a2, b0.x, acc2[r][0]);
                acc2[r][1] = fma2(a2, b0.y, acc2[r][1]);
                acc2[r][2] = fma2(a2, b1.x, acc2[r][2]);
                acc2[r][3] = fma2(a2, b1.y, acc2[r][3]);
            }
        }
        __syncthreads();
    }
    float* Cdst = ((which == 0) ? d_Z : (which == 1) ? d_ZPSI : d_P) + (size_t)head * kBT * kHD;
    #pragma unroll
    for (int r = 0; r < 8; r++) {
        int m = m0 + ty * 8 + r;
        *(ulonglong2*)&Cdst[(size_t)m * kHD + tx * 8]     = make_ulonglong2(acc2[r][0], acc2[r][1]);
        *(ulonglong2*)&Cdst[(size_t)m * kHD + tx * 8 + 4] = make_ulonglong2(acc2[r][2], acc2[r][3]);
    }
}

// ---------------- output GEMM: out[bt][d] = sum_k sum_j Q[k][bt][j] * h[k][j][d] ----------------
__global__ void __launch_bounds__(256) gemm_out_kernel(const float* __restrict__ h,
                                                       float* __restrict__ out) {
    const int n0 = blockIdx.x * 128;   // over D = 768
    const int m0 = blockIdx.y * 128;   // over BT = 4096
    __shared__ float As[16 * GP];
    __shared__ float Bs[16 * GP];
    const int tid = threadIdx.x;
    const int tx = tid & 15, ty = tid >> 4;
    ull acc2[8][4];
    #pragma unroll
    for (int r = 0; r < 8; r++)
        #pragma unroll
        for (int c = 0; c < 4; c++) acc2[r][c] = 0ULL;

    for (int k0 = 0; k0 < kNH * kHD; k0 += 16) {
        const int head = k0 >> 7;
        const int j0 = k0 & 127;
        const float* Aq = d_Q + (size_t)head * kBT * kHD;
        {
            int m = tid >> 2, kq = tid & 3;
            #pragma unroll
            for (int h2 = 0; h2 < 2; h2++) {
                int mm = m + h2 * 64;
                float4 v = *(const float4*)&Aq[(size_t)(m0 + mm) * kHD + j0 + kq * 4];
                As[(kq * 4 + 0) * GP + mm] = v.x;
                As[(kq * 4 + 1) * GP + mm] = v.y;
                As[(kq * 4 + 2) * GP + mm] = v.z;
                As[(kq * 4 + 3) * GP + mm] = v.w;
            }
        }
        {
            int f = tid;
            #pragma unroll
            for (int it = 0; it < 2; it++, f += 256) {
                int kk = f >> 5, n4 = f & 31;
                float4 v = *(const float4*)&h[(size_t)(k0 + kk) * kD + n0 + n4 * 4];
                *(float4*)&Bs[kk * GP + n4 * 4] = v;
            }
        }
        __syncthreads();
        #pragma unroll
        for (int kk = 0; kk < 16; kk++) {
            float a[8];
            *(float4*)&a[0]  = *(const float4*)&As[kk * GP + ty * 8];
            *(float4*)&a[4]  = *(const float4*)&As[kk * GP + ty * 8 + 4];
            ulonglong2 b0 = *(const ulonglong2*)&Bs[kk * GP + tx * 8];
            ulonglong2 b1 = *(const ulonglong2*)&Bs[kk * GP + tx * 8 + 4];
            #pragma unroll
            for (int r = 0; r < 8; r++) {
                ull a2 = pack2(a[r], a[r]);
                acc2[r][0] = fma2(a2, b0.x, acc2[r][0]);
                acc2[r][1] = fma2(a2, b0.y, acc2[r][1]);
                acc2[r][2] = fma2(a2, b1.x, acc2[r][2]);
                acc2[r][3] = fma2(a2, b1.y, acc2[r][3]);
            }
        }
        __syncthreads();
    }
    #pragma unroll
    for (int r = 0; r < 8; r++) {
        int m = m0 + ty * 8 + r;
        *(ulonglong2*)&out[(size_t)m * kD + n0 + tx * 8]     = make_ulonglong2(acc2[r][0], acc2[r][1]);
        *(ulonglong2*)&out[(size_t)m * kD + n0 + tx * 8 + 4] = make_ulonglong2(acc2[r][2], acc2[r][3]);
    }
}

// ---------------- the sequential scan: one CTA per (head, batch) ----------------
// Thread map: j = tid>>1 (column), half = tid&1 (row half). W and G rows for
// (column j / row j) live in registers as 32 packed f32x2 each.
constexpr int SCAN_SMEM_FLOATS =
    128 * PITCH      // G2sh (generic path only)
    + 3 * 128        // zsh (triple buffer)
    + 2 * 128        // zpsh
    + 2 * 128        // Psh
    + 8 * 128        // ysh, ppsh, Gysh, G2ysh, dysh, g1sh, v2sh, vbssh
    + 24 + 8 + 8 + 4;
constexpr int SCAN_SMEM_BYTES = SCAN_SMEM_FLOATS * 4;

__global__ void __launch_bounds__(256, 1) scan_kernel(const float* __restrict__ W0,
                                                      const float* __restrict__ Gsrc) {
    extern __shared__ float sm[];
    float* G2sh  = sm;
    float* zsh   = G2sh + 128 * PITCH;   // 3 buffers of 128
    float* zpsh  = zsh + 384;            // 2 buffers
    float* Psh   = zpsh + 256;           // 2 buffers
    float* ysh   = Psh + 256;
    float* ppsh  = ysh + 128;
    float* Gysh  = ppsh + 128;
    float* G2ysh = Gysh + 128;
    float* dysh  = G2ysh + 128;
    float* g1sh  = dysh + 128;
    float* v2sh  = g1sh + 128;
    float* vbssh = v2sh + 128;
    float* dparts = vbssh + 128;   // 5 dots x 4 warp partials (padded 24)
    float* wsumA  = dparts + 24;   // su2 partials (8 warps)
    float* wsumB  = wsumA + 8;     // q2 partials
    float* sxs    = wsumB + 8;     // SX double buffer

    const int k = blockIdx.x;
    const int b = blockIdx.y;
    const int tid = threadIdx.x;
    const int j = tid >> 1;
    const int half = tid & 1;
    const bool fast = (d_flag[0] != 0);

    // ---- init smem ----
    if (!fast) {
        for (int idx = tid; idx < kHD * kHD; idx += 256) {
            int i = idx >> 7, jj = idx & 127;
            G2sh[i * PITCH + jj] = d_G2[k * kHD * kHD + idx];
        }
    }
    const int seqbase = (k * kBT + b * kT) * kHD;
    const int tb = k * kBT + b * kT;
    if (tid < 128) {
        g1sh[tid]  = d_g1[k * kHD + tid];
        v2sh[tid]  = d_v2[k * kHD + tid];
        vbssh[tid] = d_vbs[k * kHD + tid];
        dysh[tid]  = 0.f;
        zsh[2 * 128 + tid] = 0.f;      // prev buffer at t=0 (dy=0 makes update a no-op)
        zsh[tid]  = d_Z[seqbase + tid];
        zpsh[tid] = d_ZPSI[seqbase + tid];
        Psh[tid]  = d_P[seqbase + tid];
        if (tid == 0) sxs[0] = d_SX[tb];
    }
    const float S2v  = d_S2[k];
    const float SBSv = d_SBS[k];

    // ---- W and G rows in registers (32 f32x2 each) ----
    ull W2[32], Gr[32];
    {
        const float* wsrc = W0 + (size_t)k * kHD * kHD;
        #pragma unroll
        for (int p = 0; p < 32; p++) {
            int r0 = half * 64 + 2 * p;
            W2[p] = pack2(wsrc[(size_t)r0 * kHD + j], wsrc[(size_t)(r0 + 1) * kHD + j]);
        }
        const ulonglong2* grow = (const ulonglong2*)(Gsrc + (size_t)(k * kHD + j) * kHD + half * 64);
        #pragma unroll
        for (int p = 0; p < 16; p++) {
            ulonglong2 v = grow[p];
            Gr[2 * p] = v.x; Gr[2 * p + 1] = v.y;
        }
    }
    __syncthreads();

    const float cc = (float)kNH / (float)kD;
    int prevb = 2, curb = 0, nextb = 1;

    for (int t = 0; t < kT; ++t) {
        const int cur2 = t & 1;
        const int nb2 = cur2 ^ 1;

        // ======== Stage A: W -= z_{t-1} dy^T, y = z_t@W, p = zpsi_t@W ========
        const float dyO = dysh[j];
        const ull dyn2 = pack2(-dyO, -dyO);

        // prefetch next token (hidden behind the matvec)
        float nz = 0.f, nP = 0.f, nzp = 0.f, nsx = 0.f;
        if (t + 1 < kT) {
            int pb = seqbase + (t + 1) * kHD;
            if (tid < 128) {
                nz = d_Z[pb + tid];
                nP = d_P[pb + tid];
                if (tid == 0) nsx = d_SX[tb + t + 1];
            } else {
                nzp = d_ZPSI[pb + (tid - 128)];
            }
        }

        {
            const ulonglong2* zo2 = (const ulonglong2*)(zsh + prevb * 128 + half * 64);
            const ulonglong2* zc2 = (const ulonglong2*)(zsh + curb * 128 + half * 64);
            const ulonglong2* zp2 = (const ulonglong2*)(zpsh + cur2 * 128 + half * 64);
            ull ya0 = 0ULL, ya1 = 0ULL, pa0 = 0ULL, pa1 = 0ULL;
            #pragma unroll
            for (int p = 0; p < 16; p++) {
                ulonglong2 a = zo2[p], zc = zc2[p], zp = zp2[p];
                ull w0 = fma2(a.x, dyn2, W2[2 * p]);
                ull w1 = fma2(a.y, dyn2, W2[2 * p + 1]);
                W2[2 * p] = w0; W2[2 * p + 1] = w1;
                ya0 = fma2(zc.x, w0, ya0); ya1 = fma2(zc.y, w1, ya1);
                pa0 = fma2(zp.x, w0, pa0); pa1 = fma2(zp.y, w1, pa1);
            }
            float ypart = hsum2(ya0) + hsum2(ya1);
            float ppart = hsum2(pa0) + hsum2(pa1);
            ypart += __shfl_xor_sync(0xFFFFFFFFu, ypart, 1);
            ppart += __shfl_xor_sync(0xFFFFFFFFu, ppart, 1);
            if (half == 0) { ysh[j] = ypart; ppsh[j] = ppart; }

            // stash prefetched token (distinct buffers — no race with readers)
            if (t + 1 < kT) {
                if (tid < 128) {
                    zsh[nextb * 128 + tid] = nz;
                    Psh[nb2 * 128 + tid] = nP;
                    if (tid == 0) sxs[nb2] = nsx;
                } else {
                    zpsh[nb2 * 128 + (tid - 128)] = nzp;
                }
            }
            __syncthreads();   // S1

            // ======== Stage B: Gy (G in regs, y broadcast), su2/q2 + dots ========
            const ulonglong2* y2 = (const ulonglong2*)(ysh + half * 64);
            ull ga0 = 0ULL, ga1 = 0ULL;
            #pragma unroll
            for (int p = 0; p < 16; p++) {
                ulonglong2 yv = y2[p];
                ga0 = fma2(Gr[2 * p], yv.x, ga0);
                ga1 = fma2(Gr[2 * p + 1], yv.y, ga1);
            }
            float gpart = hsum2(ga0) + hsum2(ga1);
            gpart += __shfl_xor_sync(0xFFFFFFFFu, gpart, 1);
            float g2part = gpart;
            if (!fast) {
                const ulonglong2* g2r = (const ulonglong2*)(G2sh + j * PITCH + half * 64);
                ull h0 = 0ULL, h1 = 0ULL;
                #pragma unroll
                for (int p = 0; p < 16; p++) {
                    ulonglong2 gv = g2r[p];
                    ulonglong2 yv = y2[p];
                    h0 = fma2(gv.x, yv.x, h0);
                    h1 = fma2(gv.y, yv.y, h1);
                }
                g2part = hsum2(h0) + hsum2(h1);
                g2part += __shfl_xor_sync(0xFFFFFFFFu, g2part, 1);
            }
            if (half == 0) { Gysh[j] = gpart; G2ysh[j] = g2part; }

            float su2p = (half == 0) ? gpart * ypart : 0.f;
            su2p = warpsum(su2p);
            if ((tid & 31) == 0) wsumA[tid >> 5] = su2p;
            if (!fast) {
                float q2p = (half == 0) ? g2part * ypart : 0.f;
                q2p = warpsum(q2p);
                if ((tid & 31) == 0) wsumB[tid >> 5] = q2p;
            }
        }

        if (tid < 128) {
            const int i = tid;
            float yv = ysh[i];
            float p1 = g1sh[i] * yv;
            float p2 = Psh[cur2 * 128 + i] * yv;
            float p3 = zsh[curb * 128 + i] * zpsh[cur2 * 128 + i];
            float p4 = v2sh[i] * yv;
            float p5 = vbssh[i] * yv;
            p1 = warpsum(p1); p2 = warpsum(p2); p3 = warpsum(p3);
            p4 = warpsum(p4); p5 = warpsum(p5);
            if ((tid & 31) == 0) {
                int w = tid >> 5;
                dparts[w] = p1; dparts[4 + w] = p2; dparts[8 + w] = p3;
                dparts[12 + w] = p4; dparts[16 + w] = p5;
            }
        }
        __syncthreads();   // S2

        // ======== Stage E: scalars, dy, q ========
        if (tid < 128) {
            const float g1y  = dparts[0] + dparts[1] + dparts[2] + dparts[3];
            const float Pty  = dparts[4] + dparts[5] + dparts[6] + dparts[7];
            const float zz   = dparts[8] + dparts[9] + dparts[10] + dparts[11];
            const float v2y  = dparts[12] + dparts[13] + dparts[14] + dparts[15];
            const float vbsy = dparts[16] + dparts[17] + dparts[18] + dparts[19];
            float su2 = wsumA[0] + wsumA[1] + wsumA[2] + wsumA[3]
                      + wsumA[4] + wsumA[5] + wsumA[6] + wsumA[7];
            float q2 = su2;
            if (!fast)
                q2 = wsumB[0] + wsumB[1] + wsumB[2] + wsumB[3]
                   + wsumB[4] + wsumB[5] + wsumB[6] + wsumB[7];
            const float SXt = sxs[cur2];

            const float invD = 1.f / (float)kD;
            const float mu = g1y * invD;
            const float var = su2 * invD - mu * mu;
            const float rr = rsqrtf(var + kEPS);
            const float r2 = rr * rr;
            const float mdn  = (cc * invD) * (rr * (v2y - mu * S2v) + SBSv - SXt);
            const float mdnn = (cc * invD) * (r2 * (q2 - 2.f * mu * v2y + mu * mu * S2v)
                                              + rr * (vbsy - mu * SBSv)
                                              - rr * (Pty - mu * SXt));
            const float a1 = cc * r2;
            const float a2 = -r2 * mdnn;
            const float a3 = -cc * rr;
            const float a4 = -cc * r2 * mu;
            const float a5 = cc * rr;
            const float a6 = rr * (mdnn * rr * mu - mdn);
            const int i = tid;
            float dyv = a1 * G2ysh[i] + a2 * Gysh[i] + a3 * Psh[cur2 * 128 + i]
                      + a4 * v2sh[i] + a5 * vbssh[i] + a6 * g1sh[i];
            dysh[i] = dyv;
            d_Q[seqbase + t * kHD + i] = ppsh[i] - zz * dyv;
        }
        __syncthreads();   // S3

        int tmp = prevb; prevb = curb; curb = nextb; nextb = tmp;
    }
}

// ---------------- launch ----------------
extern "C" void kernel_launch(void* const* d_in, const int* in_sizes, int n_in,
                              void* d_out, int out_size) {
    const float* X   = (const float*)d_in[0];   // batch (B,T,D)
    const float* psi = (const float*)d_in[1];   // psi_k (NH,D,HD)
    const float* phi = (const float*)d_in[2];   // phi_k (NH,D,HD)
    const float* W0  = (const float*)d_in[3];   // (NH,HD,HD)
    const float* g   = (const float*)d_in[4];   // (NH,HD,D)
    const float* h   = (const float*)d_in[5];   // (NH,HD,D) -> contiguous (768,768)
    const float* lns = (const float*)d_in[6];   // (NH,D)
    const float* lnb = (const float*)d_in[7];   // (NH,D)
    float* out = (float*)d_out;
    (void)in_sizes; (void)n_in; (void)out_size;

    // device-symbol address for d_G (needed as a kernel argument)
    float* gptr = nullptr;
    cudaGetSymbolAddress((void**)&gptr, d_G);

    cudaFuncSetAttribute(scan_kernel, cudaFuncAttributeMaxDynamicSharedMemorySize, SCAN_SMEM_BYTES);

    flag_kernel<<<1, 256>>>(lns, lnb);
    consts_kernel<<<dim3(kNH, 2), 256>>>(g, lns);
    rowstats_kernel<<<kNH, 256>>>(g, lns, lnb);
    sx_kernel<<<kBT, 192>>>(X, lns);
    gemm_proj_kernel<<<dim3(1, kBT / 128, 3 * kNH), 256>>>(X, phi, psi, g, lns);
    scan_kernel<<<dim3(kNH, kB), 256, SCAN_SMEM_BYTES>>>(W0, gptr);
    gemm_out_kernel<<<dim3(kD / 128, kBT / 128), 256>>>(h, out);
}